// round 12
// baseline (speedup 1.0000x reference)
#include <cuda_runtime.h>
#include <math.h>

#define BGR   32
#define NTOT  131072
#define NBLKX 2048
#define NBLKF 20

typedef unsigned long long u64;
union F4 { float4 v; u64 u[2]; };

__device__ __forceinline__ void fma2(u64& d, u64 a, u64 b) {
    asm("fma.rn.f32x2 %0, %1, %2, %0;" : "+l"(d) : "l"(a), "l"(b));
}
__device__ __forceinline__ float hsum2(u64 a) {
    unsigned lo, hi;
    asm("mov.b64 {%0,%1}, %2;" : "=r"(lo), "=r"(hi) : "l"(a));
    return __uint_as_float(lo) + __uint_as_float(hi);
}
__device__ __forceinline__ u64 splat2(float x) {
    u64 d; unsigned xi = __float_as_uint(x);
    asm("mov.b64 %0, {%1, %1};" : "=l"(d) : "r"(xi));
    return d;
}
__device__ __forceinline__ void unpack2(u64 a, float& lo, float& hi) {
    unsigned l_, h_;
    asm("mov.b64 {%0,%1}, %2;" : "=r"(l_), "=r"(h_) : "l"(a));
    lo = __uint_as_float(l_); hi = __uint_as_float(h_);
}

// ---------------- device scratch (no runtime alloc) ----------------
__device__ __align__(16) float g_x[(size_t)NTOT * 128];
__device__ __align__(16) float g_I[(size_t)NTOT * 40];
__device__ __align__(16) float g_ypre[1280 * 128];
__device__ __align__(16) float g_yp[BGR * 40 * 32];
__device__ __align__(16) float g_G[BGR * 32 * 32];
__device__ float g_part[NBLKX * 2];
__device__ float g_partf[NBLKF * 2];
__device__ float g_scal[4];
__device__ float g_sm[BGR * 64 * 40];
__device__ float g_ss[BGR * 64 * 40];
__device__ float g_m[BGR * 40];
__device__ float g_si[BGR * 40];

// =====================================================================
// K1: out[rows][128] = in[rows][64] @ W^T + b ; LN partial sums
// =====================================================================
struct SmG {
    float in_sh[64][68];
    float Ws[128][68];
    float bias[128];
    float red[16];
};

__global__ __launch_bounds__(256, 2) void gemm_in_kernel(
    const float* __restrict__ node, const float* __restrict__ frag,
    const float* __restrict__ Wg, const float* __restrict__ bg)
{
    extern __shared__ char smraw[];
    SmG& sm = *reinterpret_cast<SmG*>(smraw);
    const int t = threadIdx.x, w = t >> 5, l = t & 31;
    const int sel = (blockIdx.x >= NBLKX);
    const int bid = sel ? (blockIdx.x - NBLKX) : blockIdx.x;
    const size_t row0 = (size_t)bid * 64;
    const float* inp = sel ? frag : node;
    float* outp  = sel ? g_ypre : g_x;
    float* partp = sel ? g_partf : g_part;

#pragma unroll
    for (int u = 0; u < 4; ++u) {
        int id = t + 256 * u;
        int r = id >> 4, cq = id & 15;
        *reinterpret_cast<float4*>(&sm.in_sh[r][cq * 4]) =
            *reinterpret_cast<const float4*>(inp + (row0 + r) * 64 + cq * 4);
    }
#pragma unroll
    for (int u = 0; u < 8; ++u) {
        int id = t + 256 * u;
        int d = id >> 4, f4 = id & 15;
        *reinterpret_cast<float4*>(&sm.Ws[d][f4 * 4]) =
            *reinterpret_cast<const float4*>(Wg + d * 64 + f4 * 4);
    }
    if (t < 128) sm.bias[t] = bg[t];
    __syncthreads();

    u64 acc[8][4];
#pragma unroll
    for (int r = 0; r < 8; ++r)
#pragma unroll
        for (int q = 0; q < 4; ++q) acc[r][q] = 0ull;

#pragma unroll
    for (int f4 = 0; f4 < 16; ++f4) {
        int f = f4 * 4;
        F4 wq[4];
#pragma unroll
        for (int q = 0; q < 4; ++q)
            wq[q].v = *reinterpret_cast<const float4*>(&sm.Ws[l + 32 * q][f]);
#pragma unroll
        for (int r = 0; r < 8; ++r) {
            F4 xv; xv.v = *reinterpret_cast<const float4*>(&sm.in_sh[w * 8 + r][f]);
#pragma unroll
            for (int q = 0; q < 4; ++q) {
                fma2(acc[r][q], xv.u[0], wq[q].u[0]);
                fma2(acc[r][q], xv.u[1], wq[q].u[1]);
            }
        }
    }

    float s1 = 0.f, s2 = 0.f;
#pragma unroll
    for (int r = 0; r < 8; ++r) {
        float* orow = outp + (row0 + w * 8 + r) * 128;
#pragma unroll
        for (int q = 0; q < 4; ++q) {
            float v = hsum2(acc[r][q]) + sm.bias[l + 32 * q];
            orow[l + 32 * q] = v;
            s1 += v; s2 += v * v;
        }
    }
#pragma unroll
    for (int o = 16; o; o >>= 1) {
        s1 += __shfl_xor_sync(0xffffffffu, s1, o);
        s2 += __shfl_xor_sync(0xffffffffu, s2, o);
    }
    if (l == 0) { sm.red[w] = s1; sm.red[8 + w] = s2; }
    __syncthreads();
    if (t == 0) {
        float S = 0.f, Q = 0.f;
        for (int i = 0; i < 8; ++i) { S += sm.red[i]; Q += sm.red[8 + i]; }
        partp[2 * bid]     = S;
        partp[2 * bid + 1] = Q;
    }
}

// =====================================================================
// K2: finalize LN scalars
// =====================================================================
__global__ void stats_kernel()
{
    __shared__ double sh[256];
    const int t = threadIdx.x;
    double s = 0.0, q = 0.0;
    for (int i = t; i < NBLKX; i += 256) { s += (double)g_part[2 * i]; q += (double)g_part[2 * i + 1]; }

    double S, Q, Sf, Qf;
    sh[t] = s; __syncthreads();
    for (int o = 128; o; o >>= 1) { if (t < o) sh[t] += sh[t + o]; __syncthreads(); }
    S = sh[0]; __syncthreads();

    sh[t] = q; __syncthreads();
    for (int o = 128; o; o >>= 1) { if (t < o) sh[t] += sh[t + o]; __syncthreads(); }
    Q = sh[0]; __syncthreads();

    sh[t] = (t < NBLKF) ? (double)g_partf[2 * t] : 0.0; __syncthreads();
    for (int o = 128; o; o >>= 1) { if (t < o) sh[t] += sh[t + o]; __syncthreads(); }
    Sf = sh[0]; __syncthreads();

    sh[t] = (t < NBLKF) ? (double)g_partf[2 * t + 1] : 0.0; __syncthreads();
    for (int o = 128; o; o >>= 1) { if (t < o) sh[t] += sh[t + o]; __syncthreads(); }
    Qf = sh[0];

    if (t == 0) {
        double nx = 16777216.0;
        double mx = S / nx, vx = Q / nx - mx * mx;
        g_scal[0] = (float)mx;
        g_scal[1] = (float)(1.0 / sqrt(vx + 1e-5));
        double ny = 163840.0;
        double my = Sf / ny, vy = Qf / ny - my * my;
        g_scal[2] = (float)my;
        g_scal[3] = (float)(1.0 / sqrt(vy + 1e-5));
    }
}

// =====================================================================
// K3: y_p = relu(q * relu(LN(ys) @ V)); grid = 32 graphs x 5 j-chunks
// =====================================================================
__global__ __launch_bounds__(256) void yp_kernel(
    const float* __restrict__ Vg, const float* __restrict__ qg)
{
    __shared__ float ys[8][132];
    __shared__ float Vt[32][132];
    __shared__ float qs[32];
    const int b = blockIdx.x / 5, jc = blockIdx.x % 5, t = threadIdx.x;
    const int j0 = jc * 8;
    const float m = g_scal[2], rs = g_scal[3];
#pragma unroll
    for (int u = 0; u < 4; ++u) {
        int id = t + 256 * u;
        ys[id >> 7][id & 127] = (g_ypre[b * 5120 + j0 * 128 + id] - m) * rs;
    }
#pragma unroll
    for (int u = 0; u < 16; ++u) {
        int id = t + 256 * u;
        Vt[id & 31][id >> 5] = Vg[id];
    }
    if (t < 32) qs[t] = qg[t];
    __syncthreads();

    const int j = t >> 5, k = t & 31;
    u64 a0 = 0ull, a1 = 0ull;
#pragma unroll
    for (int c4 = 0; c4 < 32; c4 += 2) {
        F4 y0; y0.v = *reinterpret_cast<const float4*>(&ys[j][c4 * 4]);
        F4 v0; v0.v = *reinterpret_cast<const float4*>(&Vt[k][c4 * 4]);
        F4 y1; y1.v = *reinterpret_cast<const float4*>(&ys[j][c4 * 4 + 4]);
        F4 v1; v1.v = *reinterpret_cast<const float4*>(&Vt[k][c4 * 4 + 4]);
        fma2(a0, y0.u[0], v0.u[0]);
        fma2(a0, y0.u[1], v0.u[1]);
        fma2(a1, y1.u[0], v1.u[0]);
        fma2(a1, y1.u[1], v1.u[1]);
    }
    float a = fmaxf(hsum2(a0) + hsum2(a1), 0.f);
    a = fmaxf(qs[k] * a, 0.f);
    g_yp[b * 1280 + (j0 + j) * 32 + k] = a;
}

// =====================================================================
// K3b: per graph Gram G = y_p^T y_p (late; only final needs it)
// =====================================================================
__global__ __launch_bounds__(256) void gram_kernel()
{
    __shared__ float yps[40][33];
    const int b = blockIdx.x, t = threadIdx.x;
#pragma unroll
    for (int u = 0; u < 5; ++u) {
        int id = t + 256 * u;
        yps[id >> 5][id & 31] = g_yp[b * 1280 + id];
    }
    __syncthreads();
#pragma unroll
    for (int u = 0; u < 4; ++u) {
        int id = t + 256 * u;
        int k1 = id >> 5, k2 = id & 31;
        float acc = 0.f;
#pragma unroll
        for (int j = 0; j < 40; ++j) acc += yps[j][k1] * yps[j][k2];
        g_G[b * 1024 + id] = acc;
    }
}

// =====================================================================
// K4: layerA v2 — lane = (row, k/j-group) mapping for fewer LDS
//     wavefronts. xp: k-packed u64 accumulators, U in native [c][k].
//     I: lane owns 1 row x 10 j; softmax partials via xor-shfl semiring.
// =====================================================================
struct SmA {
    float xs[64][132];     // pitch 132: rows offset 4 banks
    float U[128][32];      // native [c][k]
    float yp[40][36];
    float xp[64][36];
    float red_m[8][40];
    float red_s[8][40];
};

__global__ __launch_bounds__(256, 3) void layerA_kernel(const float* __restrict__ Ug,
                                                        int do_norm)
{
    extern __shared__ char smraw[];
    SmA& sm = *reinterpret_cast<SmA*>(smraw);
    const int t = threadIdx.x, w = t >> 5, l = t & 31;
    const int rr = l >> 2, qq = l & 3;         // row-in-warp, k/j-group
    const int myrow = w * 8 + rr;
    const size_t row0 = (size_t)blockIdx.x * 64;
    const int b = blockIdx.x >> 6, blk = blockIdx.x & 63;

    if (do_norm) {
        const float m = g_scal[0], rs = g_scal[1];
#pragma unroll
        for (int u = 0; u < 8; ++u) {
            int id = t + 256 * u;
            int r = id >> 5, cq = id & 31;
            float* gp = g_x + (row0 + r) * 128 + cq * 4;
            float4 v = *reinterpret_cast<const float4*>(gp);
            v.x = (v.x - m) * rs; v.y = (v.y - m) * rs;
            v.z = (v.z - m) * rs; v.w = (v.w - m) * rs;
            *reinterpret_cast<float4*>(gp) = v;
            *reinterpret_cast<float4*>(&sm.xs[r][cq * 4]) = v;
        }
    } else {
#pragma unroll
        for (int u = 0; u < 8; ++u) {
            int id = t + 256 * u;
            int r = id >> 5, cq = id & 31;
            *reinterpret_cast<float4*>(&sm.xs[r][cq * 4]) =
                *reinterpret_cast<const float4*>(g_x + (row0 + r) * 128 + cq * 4);
        }
    }
#pragma unroll
    for (int u = 0; u < 4; ++u) {              // U straight copy (native)
        int id = t + 256 * u;                  // 1024 float4
        *reinterpret_cast<float4*>(&sm.U[id >> 3][(id & 7) * 4]) =
            *reinterpret_cast<const float4*>(Ug + id * 4);
    }
#pragma unroll
    for (int u = 0; u < 5; ++u) {
        int id = t + 256 * u;
        sm.yp[id >> 5][id & 31] = g_yp[b * 1280 + id];
    }
    __syncthreads();

    // ---- xp = relu(x @ U): lane owns (row myrow, k = qq*8 .. qq*8+7) ----
    {
        u64 axp[4];
#pragma unroll
        for (int p = 0; p < 4; ++p) axp[p] = 0ull;
        const int kbase = qq * 8;
#pragma unroll 8
        for (int c4 = 0; c4 < 32; ++c4) {
            int c = c4 * 4;
            F4 xv; xv.v = *reinterpret_cast<const float4*>(&sm.xs[myrow][c]);
#pragma unroll
            for (int cc = 0; cc < 4; ++cc) {
                u64 xsp = splat2((&xv.v.x)[cc]);
                F4 u0; u0.v = *reinterpret_cast<const float4*>(&sm.U[c + cc][kbase]);
                F4 u1; u1.v = *reinterpret_cast<const float4*>(&sm.U[c + cc][kbase + 4]);
                fma2(axp[0], xsp, u0.u[0]);
                fma2(axp[1], xsp, u0.u[1]);
                fma2(axp[2], xsp, u1.u[0]);
                fma2(axp[3], xsp, u1.u[1]);
            }
        }
        float f0, f1, f2, f3, f4v, f5, f6, f7;
        unpack2(axp[0], f0, f1); unpack2(axp[1], f2, f3);
        unpack2(axp[2], f4v, f5); unpack2(axp[3], f6, f7);
        float4 o0 = make_float4(fmaxf(f0, 0.f), fmaxf(f1, 0.f),
                                fmaxf(f2, 0.f), fmaxf(f3, 0.f));
        float4 o1 = make_float4(fmaxf(f4v, 0.f), fmaxf(f5, 0.f),
                                fmaxf(f6, 0.f), fmaxf(f7, 0.f));
        *reinterpret_cast<float4*>(&sm.xp[myrow][kbase])     = o0;
        *reinterpret_cast<float4*>(&sm.xp[myrow][kbase + 4]) = o1;
    }
    __syncwarp();

    // ---- I = xp @ yp^T: lane owns (row myrow, j = qq*10 .. qq*10+9) ----
    {
        u64 ai[10];
#pragma unroll
        for (int jl = 0; jl < 10; ++jl) ai[jl] = 0ull;
        const int jbase = qq * 10;
#pragma unroll
        for (int k4 = 0; k4 < 8; ++k4) {
            int k = k4 * 4;
            F4 xv; xv.v = *reinterpret_cast<const float4*>(&sm.xp[myrow][k]);
#pragma unroll
            for (int jl = 0; jl < 10; ++jl) {
                F4 yv; yv.v = *reinterpret_cast<const float4*>(&sm.yp[jbase + jl][k]);
                fma2(ai[jl], xv.u[0], yv.u[0]);
                fma2(ai[jl], xv.u[1], yv.u[1]);
            }
        }
        float iv[10];
#pragma unroll
        for (int jl = 0; jl < 10; ++jl) iv[jl] = hsum2(ai[jl]);

        float* irow = g_I + (row0 + myrow) * 40 + jbase;
#pragma unroll
        for (int jl = 0; jl < 10; ++jl) irow[jl] = iv[jl];

        // per-j (m, s) over the warp's 8 rows: reduce across rr lanes
#pragma unroll
        for (int jl = 0; jl < 10; ++jl) {
            float m = iv[jl];
            m = fmaxf(m, __shfl_xor_sync(0xffffffffu, m, 4));
            m = fmaxf(m, __shfl_xor_sync(0xffffffffu, m, 8));
            m = fmaxf(m, __shfl_xor_sync(0xffffffffu, m, 16));
            float e = __expf(iv[jl] - m);
            e += __shfl_xor_sync(0xffffffffu, e, 4);
            e += __shfl_xor_sync(0xffffffffu, e, 8);
            e += __shfl_xor_sync(0xffffffffu, e, 16);
            if (rr == 0) {
                sm.red_m[w][jbase + jl] = m;
                sm.red_s[w][jbase + jl] = e;
            }
        }
    }
    __syncthreads();

    if (t < 40) {
        float m = sm.red_m[0][t], s = sm.red_s[0][t];
#pragma unroll
        for (int ww = 1; ww < 8; ++ww) {
            float bm = sm.red_m[ww][t], bs = sm.red_s[ww][t];
            float mn = fmaxf(m, bm);
            s = s * __expf(m - mn) + bs * __expf(bm - mn);
            m = mn;
        }
        int idx = (b * 64 + blk) * 40 + t;
        g_sm[idx] = m; g_ss[idx] = s;
    }
}

// =====================================================================
// K5: merge softmax partials — one warp per (b,j); grid 160 x 256
// =====================================================================
__global__ __launch_bounds__(256) void merge_kernel()
{
    const int t = threadIdx.x, w = t >> 5, l = t & 31;
    const int widx = blockIdx.x * 8 + w;
    const int b = widx / 40, j = widx % 40;
    float m1 = g_sm[(b * 64 + l) * 40 + j];
    float s1 = g_ss[(b * 64 + l) * 40 + j];
    float m2 = g_sm[(b * 64 + l + 32) * 40 + j];
    float s2 = g_ss[(b * 64 + l + 32) * 40 + j];
    float m = fmaxf(m1, m2);
    float s = s1 * __expf(m1 - m) + s2 * __expf(m2 - m);
#pragma unroll
    for (int o = 16; o; o >>= 1) {
        float bm = __shfl_xor_sync(0xffffffffu, m, o);
        float bs = __shfl_xor_sync(0xffffffffu, s, o);
        float mn = fmaxf(m, bm);
        s = s * __expf(m - mn) + bs * __expf(bm - mn);
        m = mn;
    }
    if (l == 0) {
        g_m[b * 40 + j]  = m;
        g_si[b * 40 + j] = 1.f / s;
    }
}

// =====================================================================
// K6: layerB — EXACT R9 kernel (journal rule: do not modify)
// =====================================================================
struct SmB {
    float xs[64][128];
    float a[64][44];
    float ypT[32][44];
    float Vs[128][36];
    float h[64][36];
    float gw[256];
    float gb;
};

__global__ __launch_bounds__(256, 2) void layerB_kernel(
    const float* __restrict__ Vg, const float* __restrict__ gWp,
    const float* __restrict__ gBp)
{
    extern __shared__ char smraw[];
    SmB& sm = *reinterpret_cast<SmB*>(smraw);
    const int t = threadIdx.x, w = t >> 5, l = t & 31;
    const size_t row0 = (size_t)blockIdx.x * 64;
    const int b = blockIdx.x >> 6;

#pragma unroll
    for (int u = 0; u < 8; ++u) {
        int id = t + 256 * u;
        int r = id >> 5, cq = id & 31;
        *reinterpret_cast<float4*>(&sm.xs[r][cq * 4]) =
            *reinterpret_cast<const float4*>(g_x + (row0 + r) * 128 + cq * 4);
    }
#pragma unroll
    for (int u = 0; u < 4; ++u) {
        int id = t + 256 * u;
        int d = id >> 3, k4 = id & 7;
        *reinterpret_cast<float4*>(&sm.Vs[d][k4 * 4]) =
            *reinterpret_cast<const float4*>(Vg + d * 32 + k4 * 4);
    }
#pragma unroll
    for (int u = 0; u < 5; ++u) {
        int id = t + 256 * u;
        sm.ypT[id & 31][id >> 5] = g_yp[b * 1280 + id];
    }
    sm.gw[t] = gWp[t];
    if (t == 0) sm.gb = gBp[0];
#pragma unroll
    for (int u = 0; u < 10; ++u) {
        int id = t + 256 * u;
        int r = id / 40, j = id - r * 40;
        float v = g_I[row0 * 40 + id];
        sm.a[r][j] = __expf(v - g_m[b * 40 + j]) * g_si[b * 40 + j];
    }
    __syncthreads();

    {
        u64 acc[8];
#pragma unroll
        for (int r = 0; r < 8; ++r) acc[r] = 0ull;
#pragma unroll
        for (int j4 = 0; j4 < 10; ++j4) {
            int j = j4 * 4;
            F4 yv; yv.v = *reinterpret_cast<const float4*>(&sm.ypT[l][j]);
#pragma unroll
            for (int r = 0; r < 8; ++r) {
                F4 av; av.v = *reinterpret_cast<const float4*>(&sm.a[w * 8 + r][j]);
                fma2(acc[r], av.u[0], yv.u[0]);
                fma2(acc[r], av.u[1], yv.u[1]);
            }
        }
#pragma unroll
        for (int r = 0; r < 8; ++r) sm.h[w * 8 + r][l] = fmaxf(hsum2(acc[r]), 0.f);
    }
    __syncwarp();

    {
        u64 acc[8][4];
#pragma unroll
        for (int r = 0; r < 8; ++r)
#pragma unroll
            for (int q = 0; q < 4; ++q) acc[r][q] = 0ull;

#pragma unroll
        for (int k4 = 0; k4 < 8; ++k4) {
            int k = 4 * k4;
            F4 vq[4];
#pragma unroll
            for (int q = 0; q < 4; ++q)
                vq[q].v = *reinterpret_cast<const float4*>(&sm.Vs[l + 32 * q][k]);
#pragma unroll
            for (int r = 0; r < 8; ++r) {
                F4 hv; hv.v = *reinterpret_cast<const float4*>(&sm.h[w * 8 + r][k]);
#pragma unroll
                for (int q = 0; q < 4; ++q) {
                    fma2(acc[r][q], hv.u[0], vq[q].u[0]);
                    fma2(acc[r][q], hv.u[1], vq[q].u[1]);
                }
            }
        }
        float gb = sm.gb;
#pragma unroll
        for (int r = 0; r < 8; ++r) {
            float gp = 0.f;
            float xv[4], hc[4];
#pragma unroll
            for (int q = 0; q < 4; ++q) {
                int d = l + 32 * q;
                hc[q] = hsum2(acc[r][q]);
                xv[q] = sm.xs[w * 8 + r][d];
                gp += xv[q] * sm.gw[d] + hc[q] * sm.gw[128 + d];
            }
#pragma unroll
            for (int o = 16; o; o >>= 1) gp += __shfl_xor_sync(0xffffffffu, gp, o);
            float z = 1.f / (1.f + __expf(-(gp + gb)));
            float* orow = g_x + (row0 + w * 8 + r) * 128;
#pragma unroll
            for (int q = 0; q < 4; ++q) {
                int d = l + 32 * q;
                orow[d] = (1.f - z) * xv[q] + z * hc[q];
            }
        }
    }
}

// =====================================================================
// K7: final — xp = relu(x@U); out = sigmoid(xp^T G xp)  (G symmetric)
// =====================================================================
struct SmF {
    float xs[64][128];
    float Ut[32][132];
    float G[32][36];
    float xp[64][36];
};

__global__ __launch_bounds__(256, 3) void final_kernel(
    const float* __restrict__ Ug, float* __restrict__ out)
{
    extern __shared__ char smraw[];
    SmF& sm = *reinterpret_cast<SmF*>(smraw);
    const int t = threadIdx.x, w = t >> 5, l = t & 31;
    const size_t row0 = (size_t)blockIdx.x * 64;
    const int b = blockIdx.x >> 6;

#pragma unroll
    for (int u = 0; u < 8; ++u) {
        int id = t + 256 * u;
        int r = id >> 5, cq = id & 31;
        *reinterpret_cast<float4*>(&sm.xs[r][cq * 4]) =
            *reinterpret_cast<const float4*>(g_x + (row0 + r) * 128 + cq * 4);
    }
#pragma unroll
    for (int u = 0; u < 16; ++u) {
        int id = t + 256 * u;
        sm.Ut[id & 31][id >> 5] = Ug[id];
    }
#pragma unroll
    for (int u = 0; u < 4; ++u) {
        int id = t + 256 * u;
        int k1 = id >> 5, k2 = id & 31;
        sm.G[k1][k2] = g_G[b * 1024 + id];
    }
    __syncthreads();

    {
        u64 acc[8];
#pragma unroll
        for (int r = 0; r < 8; ++r) acc[r] = 0ull;
#pragma unroll
        for (int c4 = 0; c4 < 32; ++c4) {
            int c = c4 * 4;
            F4 uv; uv.v = *reinterpret_cast<const float4*>(&sm.Ut[l][c]);
#pragma unroll
            for (int r = 0; r < 8; ++r) {
                F4 xv; xv.v = *reinterpret_cast<const float4*>(&sm.xs[w * 8 + r][c]);
                fma2(acc[r], xv.u[0], uv.u[0]);
                fma2(acc[r], xv.u[1], uv.u[1]);
            }
        }
#pragma unroll
        for (int r = 0; r < 8; ++r) sm.xp[w * 8 + r][l] = fmaxf(hsum2(acc[r]), 0.f);
    }
    __syncwarp();

    {
        u64 acc[8];
#pragma unroll
        for (int r = 0; r < 8; ++r) acc[r] = 0ull;
#pragma unroll
        for (int k14 = 0; k14 < 8; ++k14) {
            int k1 = 4 * k14;
            F4 gv; gv.v = *reinterpret_cast<const float4*>(&sm.G[l][k1]);
#pragma unroll
            for (int r = 0; r < 8; ++r) {
                F4 xv; xv.v = *reinterpret_cast<const float4*>(&sm.xp[w * 8 + r][k1]);
                fma2(acc[r], xv.u[0], gv.u[0]);
                fma2(acc[r], xv.u[1], gv.u[1]);
            }
        }
#pragma unroll
        for (int r = 0; r < 8; ++r) {
            float v = sm.xp[w * 8 + r][l] * hsum2(acc[r]);
#pragma unroll
            for (int o = 16; o; o >>= 1) v += __shfl_xor_sync(0xffffffffu, v, o);
            if (l == 0) out[row0 + w * 8 + r] = 1.f / (1.f + __expf(-v));
        }
    }
}

// =====================================================================
extern "C" void kernel_launch(void* const* d_in, const int* in_sizes, int n_in,
                              void* d_out, int out_size)
{
    const float* node = (const float*)d_in[0];
    const float* frag = (const float*)d_in[1];
    const float* Wg   = (const float*)d_in[2];
    const float* bg   = (const float*)d_in[3];
    const float* Ug   = (const float*)d_in[4];
    const float* Vg   = (const float*)d_in[5];
    const float* qg   = (const float*)d_in[6];
    const float* gW   = (const float*)d_in[7];
    const float* gB   = (const float*)d_in[8];
    float* out = (float*)d_out;

    cudaFuncSetAttribute(gemm_in_kernel, cudaFuncAttributeMaxDynamicSharedMemorySize, (int)sizeof(SmG));
    cudaFuncSetAttribute(layerA_kernel,  cudaFuncAttributeMaxDynamicSharedMemorySize, (int)sizeof(SmA));
    cudaFuncSetAttribute(layerB_kernel,  cudaFuncAttributeMaxDynamicSharedMemorySize, (int)sizeof(SmB));
    cudaFuncSetAttribute(final_kernel,   cudaFuncAttributeMaxDynamicSharedMemorySize, (int)sizeof(SmF));

    gemm_in_kernel<<<NBLKX + NBLKF, 256, sizeof(SmG)>>>(node, frag, Wg, bg);
    stats_kernel<<<1, 256>>>();
    yp_kernel<<<BGR * 5, 256>>>(Vg, qg);
    layerA_kernel<<<NBLKX, 256, sizeof(SmA)>>>(Ug, 1);   // launch #4 -> profiled
    merge_kernel<<<160, 256>>>();
    layerB_kernel<<<NBLKX, 256, sizeof(SmB)>>>(Vg, gW, gB);
    layerA_kernel<<<NBLKX, 256, sizeof(SmA)>>>(Ug, 0);
    merge_kernel<<<160, 256>>>();
    layerB_kernel<<<NBLKX, 256, sizeof(SmB)>>>(Vg, gW, gB);
    gram_kernel<<<BGR, 256>>>();
    final_kernel<<<NBLKX, 256, sizeof(SmF)>>>(Ug, out);
}

// round 13
// speedup vs baseline: 1.7627x; 1.7627x over previous
#include <cuda_runtime.h>
#include <math.h>

#define BGR   32
#define NTOT  131072
#define NBLKX 2048
#define NBLKF 20

typedef unsigned long long u64;
union F4 { float4 v; u64 u[2]; };

__device__ __forceinline__ void fma2(u64& d, u64 a, u64 b) {
    asm("fma.rn.f32x2 %0, %1, %2, %0;" : "+l"(d) : "l"(a), "l"(b));
}
__device__ __forceinline__ float hsum2(u64 a) {
    unsigned lo, hi;
    asm("mov.b64 {%0,%1}, %2;" : "=r"(lo), "=r"(hi) : "l"(a));
    return __uint_as_float(lo) + __uint_as_float(hi);
}

// ---------------- device scratch (no runtime alloc) ----------------
__device__ __align__(16) float g_x[(size_t)NTOT * 128];
__device__ __align__(16) float g_I[(size_t)NTOT * 40];
__device__ __align__(16) float g_ypre[1280 * 128];
__device__ __align__(16) float g_yp[BGR * 40 * 32];
__device__ float g_part[NBLKX * 2];
__device__ float g_partf[NBLKF * 2];
__device__ float g_scal[4];
__device__ float g_sm[BGR * 64 * 40];
__device__ float g_ss[BGR * 64 * 40];
__device__ float g_m[BGR * 40];
__device__ float g_si[BGR * 40];

// =====================================================================
// K1: out[rows][128] = in[rows][64] @ W^T + b ; LN partial sums
// =====================================================================
struct SmG {
    float in_sh[64][68];
    float Ws[128][68];
    float bias[128];
    float red[16];
};

__global__ __launch_bounds__(256, 2) void gemm_in_kernel(
    const float* __restrict__ node, const float* __restrict__ frag,
    const float* __restrict__ Wg, const float* __restrict__ bg)
{
    extern __shared__ char smraw[];
    SmG& sm = *reinterpret_cast<SmG*>(smraw);
    const int t = threadIdx.x, w = t >> 5, l = t & 31;
    const int sel = (blockIdx.x >= NBLKX);
    const int bid = sel ? (blockIdx.x - NBLKX) : blockIdx.x;
    const size_t row0 = (size_t)bid * 64;
    const float* inp = sel ? frag : node;
    float* outp  = sel ? g_ypre : g_x;
    float* partp = sel ? g_partf : g_part;

#pragma unroll
    for (int u = 0; u < 4; ++u) {
        int id = t + 256 * u;
        int r = id >> 4, cq = id & 15;
        *reinterpret_cast<float4*>(&sm.in_sh[r][cq * 4]) =
            *reinterpret_cast<const float4*>(inp + (row0 + r) * 64 + cq * 4);
    }
#pragma unroll
    for (int u = 0; u < 8; ++u) {
        int id = t + 256 * u;
        int d = id >> 4, f4 = id & 15;
        *reinterpret_cast<float4*>(&sm.Ws[d][f4 * 4]) =
            *reinterpret_cast<const float4*>(Wg + d * 64 + f4 * 4);
    }
    if (t < 128) sm.bias[t] = bg[t];
    __syncthreads();

    u64 acc[8][4];
#pragma unroll
    for (int r = 0; r < 8; ++r)
#pragma unroll
        for (int q = 0; q < 4; ++q) acc[r][q] = 0ull;

#pragma unroll
    for (int f4 = 0; f4 < 16; ++f4) {
        int f = f4 * 4;
        F4 wq[4];
#pragma unroll
        for (int q = 0; q < 4; ++q)
            wq[q].v = *reinterpret_cast<const float4*>(&sm.Ws[l + 32 * q][f]);
#pragma unroll
        for (int r = 0; r < 8; ++r) {
            F4 xv; xv.v = *reinterpret_cast<const float4*>(&sm.in_sh[w * 8 + r][f]);
#pragma unroll
            for (int q = 0; q < 4; ++q) {
                fma2(acc[r][q], xv.u[0], wq[q].u[0]);
                fma2(acc[r][q], xv.u[1], wq[q].u[1]);
            }
        }
    }

    float s1 = 0.f, s2 = 0.f;
#pragma unroll
    for (int r = 0; r < 8; ++r) {
        float* orow = outp + (row0 + w * 8 + r) * 128;
#pragma unroll
        for (int q = 0; q < 4; ++q) {
            float v = hsum2(acc[r][q]) + sm.bias[l + 32 * q];
            orow[l + 32 * q] = v;
            s1 += v; s2 += v * v;
        }
    }
#pragma unroll
    for (int o = 16; o; o >>= 1) {
        s1 += __shfl_xor_sync(0xffffffffu, s1, o);
        s2 += __shfl_xor_sync(0xffffffffu, s2, o);
    }
    if (l == 0) { sm.red[w] = s1; sm.red[8 + w] = s2; }
    __syncthreads();
    if (t == 0) {
        float S = 0.f, Q = 0.f;
        for (int i = 0; i < 8; ++i) { S += sm.red[i]; Q += sm.red[8 + i]; }
        partp[2 * bid]     = S;
        partp[2 * bid + 1] = Q;
    }
}

// =====================================================================
// K2: finalize LN scalars
// =====================================================================
__global__ void stats_kernel()
{
    __shared__ double sh[256];
    const int t = threadIdx.x;
    double s = 0.0, q = 0.0;
    for (int i = t; i < NBLKX; i += 256) { s += (double)g_part[2 * i]; q += (double)g_part[2 * i + 1]; }

    double S, Q, Sf, Qf;
    sh[t] = s; __syncthreads();
    for (int o = 128; o; o >>= 1) { if (t < o) sh[t] += sh[t + o]; __syncthreads(); }
    S = sh[0]; __syncthreads();

    sh[t] = q; __syncthreads();
    for (int o = 128; o; o >>= 1) { if (t < o) sh[t] += sh[t + o]; __syncthreads(); }
    Q = sh[0]; __syncthreads();

    sh[t] = (t < NBLKF) ? (double)g_partf[2 * t] : 0.0; __syncthreads();
    for (int o = 128; o; o >>= 1) { if (t < o) sh[t] += sh[t + o]; __syncthreads(); }
    Sf = sh[0]; __syncthreads();

    sh[t] = (t < NBLKF) ? (double)g_partf[2 * t + 1] : 0.0; __syncthreads();
    for (int o = 128; o; o >>= 1) { if (t < o) sh[t] += sh[t + o]; __syncthreads(); }
    Qf = sh[0];

    if (t == 0) {
        double nx = 16777216.0;
        double mx = S / nx, vx = Q / nx - mx * mx;
        g_scal[0] = (float)mx;
        g_scal[1] = (float)(1.0 / sqrt(vx + 1e-5));
        double ny = 163840.0;
        double my = Sf / ny, vy = Qf / ny - my * my;
        g_scal[2] = (float)my;
        g_scal[3] = (float)(1.0 / sqrt(vy + 1e-5));
    }
}

// =====================================================================
// K3: y_p = relu(q * relu(LN(ys) @ V)); grid = 32 graphs x 5 j-chunks
// =====================================================================
__global__ __launch_bounds__(256) void yp_kernel(
    const float* __restrict__ Vg, const float* __restrict__ qg)
{
    __shared__ float ys[8][132];
    __shared__ float Vt[32][132];
    __shared__ float qs[32];
    const int b = blockIdx.x / 5, jc = blockIdx.x % 5, t = threadIdx.x;
    const int j0 = jc * 8;
    const float m = g_scal[2], rs = g_scal[3];
#pragma unroll
    for (int u = 0; u < 4; ++u) {
        int id = t + 256 * u;
        ys[id >> 7][id & 127] = (g_ypre[b * 5120 + j0 * 128 + id] - m) * rs;
    }
#pragma unroll
    for (int u = 0; u < 16; ++u) {
        int id = t + 256 * u;
        Vt[id & 31][id >> 5] = Vg[id];
    }
    if (t < 32) qs[t] = qg[t];
    __syncthreads();

    const int j = t >> 5, k = t & 31;
    u64 a0 = 0ull, a1 = 0ull;
#pragma unroll
    for (int c4 = 0; c4 < 32; c4 += 2) {
        F4 y0; y0.v = *reinterpret_cast<const float4*>(&ys[j][c4 * 4]);
        F4 v0; v0.v = *reinterpret_cast<const float4*>(&Vt[k][c4 * 4]);
        F4 y1; y1.v = *reinterpret_cast<const float4*>(&ys[j][c4 * 4 + 4]);
        F4 v1; v1.v = *reinterpret_cast<const float4*>(&Vt[k][c4 * 4 + 4]);
        fma2(a0, y0.u[0], v0.u[0]);
        fma2(a0, y0.u[1], v0.u[1]);
        fma2(a1, y1.u[0], v1.u[0]);
        fma2(a1, y1.u[1], v1.u[1]);
    }
    float a = fmaxf(hsum2(a0) + hsum2(a1), 0.f);
    a = fmaxf(qs[k] * a, 0.f);
    g_yp[b * 1280 + (j0 + j) * 32 + k] = a;
}

// =====================================================================
// K4: layerA — R9-PROVEN kernel (journal: do not restructure)
// =====================================================================
struct SmA {
    float xs[64][128];
    float Ut[32][132];
    float yp[40][36];
    float xp[64][36];
    float red_m[8][40];
    float red_s[8][40];
};

__global__ __launch_bounds__(256, 3) void layerA_kernel(const float* __restrict__ Ug,
                                                        int do_norm)
{
    extern __shared__ char smraw[];
    SmA& sm = *reinterpret_cast<SmA*>(smraw);
    const int t = threadIdx.x, w = t >> 5, l = t & 31;
    const size_t row0 = (size_t)blockIdx.x * 64;
    const int b = blockIdx.x >> 6, blk = blockIdx.x & 63;

    if (do_norm) {
        const float m = g_scal[0], rs = g_scal[1];
#pragma unroll
        for (int u = 0; u < 8; ++u) {
            int id = t + 256 * u;
            int r = id >> 5, cq = id & 31;
            float* gp = g_x + (row0 + r) * 128 + cq * 4;
            float4 v = *reinterpret_cast<const float4*>(gp);
            v.x = (v.x - m) * rs; v.y = (v.y - m) * rs;
            v.z = (v.z - m) * rs; v.w = (v.w - m) * rs;
            *reinterpret_cast<float4*>(gp) = v;
            *reinterpret_cast<float4*>(&sm.xs[r][cq * 4]) = v;
        }
    } else {
#pragma unroll
        for (int u = 0; u < 8; ++u) {
            int id = t + 256 * u;
            int r = id >> 5, cq = id & 31;
            *reinterpret_cast<float4*>(&sm.xs[r][cq * 4]) =
                *reinterpret_cast<const float4*>(g_x + (row0 + r) * 128 + cq * 4);
        }
    }
#pragma unroll
    for (int u = 0; u < 16; ++u) {
        int id = t + 256 * u;
        sm.Ut[id & 31][id >> 5] = Ug[id];
    }
#pragma unroll
    for (int u = 0; u < 5; ++u) {
        int id = t + 256 * u;
        sm.yp[id >> 5][id & 31] = g_yp[b * 1280 + id];
    }
    __syncthreads();

    // xp = relu(x @ U)
    {
        u64 acc[8];
#pragma unroll
        for (int r = 0; r < 8; ++r) acc[r] = 0ull;
#pragma unroll
        for (int c4 = 0; c4 < 32; ++c4) {
            int c = c4 * 4;
            F4 uv; uv.v = *reinterpret_cast<const float4*>(&sm.Ut[l][c]);
#pragma unroll
            for (int r = 0; r < 8; ++r) {
                F4 xv; xv.v = *reinterpret_cast<const float4*>(&sm.xs[w * 8 + r][c]);
                fma2(acc[r], xv.u[0], uv.u[0]);
                fma2(acc[r], xv.u[1], uv.u[1]);
            }
        }
#pragma unroll
        for (int r = 0; r < 8; ++r) sm.xp[w * 8 + r][l] = fmaxf(hsum2(acc[r]), 0.f);
    }
    __syncwarp();

    // I = xp @ yp^T
    {
        const int j0 = l;
        const bool has1 = (l < 8);
        const int j1 = has1 ? (l + 32) : 39;
        u64 a0[8], a1[8];
#pragma unroll
        for (int r = 0; r < 8; ++r) { a0[r] = 0ull; a1[r] = 0ull; }
#pragma unroll
        for (int k4 = 0; k4 < 8; ++k4) {
            int k = k4 * 4;
            F4 y0; y0.v = *reinterpret_cast<const float4*>(&sm.yp[j0][k]);
            F4 y1; y1.v = *reinterpret_cast<const float4*>(&sm.yp[j1][k]);
#pragma unroll
            for (int r = 0; r < 8; ++r) {
                F4 xv; xv.v = *reinterpret_cast<const float4*>(&sm.xp[w * 8 + r][k]);
                fma2(a0[r], xv.u[0], y0.u[0]);
                fma2(a0[r], xv.u[1], y0.u[1]);
                fma2(a1[r], xv.u[0], y1.u[0]);
                fma2(a1[r], xv.u[1], y1.u[1]);
            }
        }
        float i0[8], i1[8];
#pragma unroll
        for (int r = 0; r < 8; ++r) { i0[r] = hsum2(a0[r]); i1[r] = hsum2(a1[r]); }
        float m0 = -1e30f, m1 = -1e30f;
#pragma unroll
        for (int r = 0; r < 8; ++r) { m0 = fmaxf(m0, i0[r]); m1 = fmaxf(m1, i1[r]); }
        float s0 = 0.f, s1v = 0.f;
#pragma unroll
        for (int r = 0; r < 8; ++r) { s0 += __expf(i0[r] - m0); s1v += __expf(i1[r] - m1); }
#pragma unroll
        for (int r = 0; r < 8; ++r) {
            size_t row = row0 + w * 8 + r;
            g_I[row * 40 + j0] = i0[r];
            if (has1) g_I[row * 40 + j1] = i1[r];
        }
        sm.red_m[w][j0] = m0; sm.red_s[w][j0] = s0;
        if (has1) { sm.red_m[w][j1] = m1; sm.red_s[w][j1] = s1v; }
    }
    __syncthreads();

    if (t < 40) {
        float m = sm.red_m[0][t], s = sm.red_s[0][t];
#pragma unroll
        for (int ww = 1; ww < 8; ++ww) {
            float bm = sm.red_m[ww][t], bs = sm.red_s[ww][t];
            float mn = fmaxf(m, bm);
            s = s * __expf(m - mn) + bs * __expf(bm - mn);
            m = mn;
        }
        int idx = (b * 64 + blk) * 40 + t;
        g_sm[idx] = m; g_ss[idx] = s;
    }
}

// =====================================================================
// K5: merge softmax partials — one warp per (b,j); grid 160 x 256
// =====================================================================
__global__ __launch_bounds__(256) void merge_kernel()
{
    const int t = threadIdx.x, w = t >> 5, l = t & 31;
    const int widx = blockIdx.x * 8 + w;
    const int b = widx / 40, j = widx % 40;
    float m1 = g_sm[(b * 64 + l) * 40 + j];
    float s1 = g_ss[(b * 64 + l) * 40 + j];
    float m2 = g_sm[(b * 64 + l + 32) * 40 + j];
    float s2 = g_ss[(b * 64 + l + 32) * 40 + j];
    float m = fmaxf(m1, m2);
    float s = s1 * __expf(m1 - m) + s2 * __expf(m2 - m);
#pragma unroll
    for (int o = 16; o; o >>= 1) {
        float bm = __shfl_xor_sync(0xffffffffu, m, o);
        float bs = __shfl_xor_sync(0xffffffffu, s, o);
        float mn = fmaxf(m, bm);
        s = s * __expf(m - mn) + bs * __expf(bm - mn);
        m = mn;
    }
    if (l == 0) {
        g_m[b * 40 + j]  = m;
        g_si[b * 40 + j] = 1.f / s;
    }
}

// =====================================================================
// K6: layerB — EXACT R9 kernel (journal rule: do not modify)
// =====================================================================
struct SmB {
    float xs[64][128];
    float a[64][44];
    float ypT[32][44];
    float Vs[128][36];
    float h[64][36];
    float gw[256];
    float gb;
};

__global__ __launch_bounds__(256, 2) void layerB_kernel(
    const float* __restrict__ Vg, const float* __restrict__ gWp,
    const float* __restrict__ gBp)
{
    extern __shared__ char smraw[];
    SmB& sm = *reinterpret_cast<SmB*>(smraw);
    const int t = threadIdx.x, w = t >> 5, l = t & 31;
    const size_t row0 = (size_t)blockIdx.x * 64;
    const int b = blockIdx.x >> 6;

#pragma unroll
    for (int u = 0; u < 8; ++u) {
        int id = t + 256 * u;
        int r = id >> 5, cq = id & 31;
        *reinterpret_cast<float4*>(&sm.xs[r][cq * 4]) =
            *reinterpret_cast<const float4*>(g_x + (row0 + r) * 128 + cq * 4);
    }
#pragma unroll
    for (int u = 0; u < 4; ++u) {
        int id = t + 256 * u;
        int d = id >> 3, k4 = id & 7;
        *reinterpret_cast<float4*>(&sm.Vs[d][k4 * 4]) =
            *reinterpret_cast<const float4*>(Vg + d * 32 + k4 * 4);
    }
#pragma unroll
    for (int u = 0; u < 5; ++u) {
        int id = t + 256 * u;
        sm.ypT[id & 31][id >> 5] = g_yp[b * 1280 + id];
    }
    sm.gw[t] = gWp[t];
    if (t == 0) sm.gb = gBp[0];
#pragma unroll
    for (int u = 0; u < 10; ++u) {
        int id = t + 256 * u;
        int r = id / 40, j = id - r * 40;
        float v = g_I[row0 * 40 + id];
        sm.a[r][j] = __expf(v - g_m[b * 40 + j]) * g_si[b * 40 + j];
    }
    __syncthreads();

    {
        u64 acc[8];
#pragma unroll
        for (int r = 0; r < 8; ++r) acc[r] = 0ull;
#pragma unroll
        for (int j4 = 0; j4 < 10; ++j4) {
            int j = j4 * 4;
            F4 yv; yv.v = *reinterpret_cast<const float4*>(&sm.ypT[l][j]);
#pragma unroll
            for (int r = 0; r < 8; ++r) {
                F4 av; av.v = *reinterpret_cast<const float4*>(&sm.a[w * 8 + r][j]);
                fma2(acc[r], av.u[0], yv.u[0]);
                fma2(acc[r], av.u[1], yv.u[1]);
            }
        }
#pragma unroll
        for (int r = 0; r < 8; ++r) sm.h[w * 8 + r][l] = fmaxf(hsum2(acc[r]), 0.f);
    }
    __syncwarp();

    {
        u64 acc[8][4];
#pragma unroll
        for (int r = 0; r < 8; ++r)
#pragma unroll
            for (int q = 0; q < 4; ++q) acc[r][q] = 0ull;

#pragma unroll
        for (int k4 = 0; k4 < 8; ++k4) {
            int k = 4 * k4;
            F4 vq[4];
#pragma unroll
            for (int q = 0; q < 4; ++q)
                vq[q].v = *reinterpret_cast<const float4*>(&sm.Vs[l + 32 * q][k]);
#pragma unroll
            for (int r = 0; r < 8; ++r) {
                F4 hv; hv.v = *reinterpret_cast<const float4*>(&sm.h[w * 8 + r][k]);
#pragma unroll
                for (int q = 0; q < 4; ++q) {
                    fma2(acc[r][q], hv.u[0], vq[q].u[0]);
                    fma2(acc[r][q], hv.u[1], vq[q].u[1]);
                }
            }
        }
        float gb = sm.gb;
#pragma unroll
        for (int r = 0; r < 8; ++r) {
            float gp = 0.f;
            float xv[4], hc[4];
#pragma unroll
            for (int q = 0; q < 4; ++q) {
                int d = l + 32 * q;
                hc[q] = hsum2(acc[r][q]);
                xv[q] = sm.xs[w * 8 + r][d];
                gp += xv[q] * sm.gw[d] + hc[q] * sm.gw[128 + d];
            }
#pragma unroll
            for (int o = 16; o; o >>= 1) gp += __shfl_xor_sync(0xffffffffu, gp, o);
            float z = 1.f / (1.f + __expf(-(gp + gb)));
            float* orow = g_x + (row0 + w * 8 + r) * 128;
#pragma unroll
            for (int q = 0; q < 4; ++q) {
                int d = l + 32 * q;
                orow[d] = (1.f - z) * xv[q] + z * hc[q];
            }
        }
    }
}

// =====================================================================
// K7: final — computes G = yp^T yp in-block (gram kernel folded in),
//     xp = relu(x@U), out = sigmoid(xp^T G xp)
// =====================================================================
struct SmF {
    float xs[64][128];
    float Ut[32][132];
    float yps[40][36];
    float G[32][36];
    float xp[64][36];
};

__global__ __launch_bounds__(256, 3) void final_kernel(
    const float* __restrict__ Ug, float* __restrict__ out)
{
    extern __shared__ char smraw[];
    SmF& sm = *reinterpret_cast<SmF*>(smraw);
    const int t = threadIdx.x, w = t >> 5, l = t & 31;
    const size_t row0 = (size_t)blockIdx.x * 64;
    const int b = blockIdx.x >> 6;

#pragma unroll
    for (int u = 0; u < 8; ++u) {
        int id = t + 256 * u;
        int r = id >> 5, cq = id & 31;
        *reinterpret_cast<float4*>(&sm.xs[r][cq * 4]) =
            *reinterpret_cast<const float4*>(g_x + (row0 + r) * 128 + cq * 4);
    }
#pragma unroll
    for (int u = 0; u < 16; ++u) {
        int id = t + 256 * u;
        sm.Ut[id & 31][id >> 5] = Ug[id];
    }
#pragma unroll
    for (int u = 0; u < 5; ++u) {
        int id = t + 256 * u;
        sm.yps[id >> 5][id & 31] = g_yp[b * 1280 + id];
    }
    __syncthreads();

    // G = yp^T yp  (same accumulation order as the old gram kernel)
#pragma unroll
    for (int u = 0; u < 4; ++u) {
        int id = t + 256 * u;
        int k1 = id >> 5, k2 = id & 31;
        float acc = 0.f;
#pragma unroll
        for (int j = 0; j < 40; ++j) acc += sm.yps[j][k1] * sm.yps[j][k2];
        sm.G[k1][k2] = acc;
    }

    // xp = relu(x @ U)
    {
        u64 acc[8];
#pragma unroll
        for (int r = 0; r < 8; ++r) acc[r] = 0ull;
#pragma unroll
        for (int c4 = 0; c4 < 32; ++c4) {
            int c = c4 * 4;
            F4 uv; uv.v = *reinterpret_cast<const float4*>(&sm.Ut[l][c]);
#pragma unroll
            for (int r = 0; r < 8; ++r) {
                F4 xv; xv.v = *reinterpret_cast<const float4*>(&sm.xs[w * 8 + r][c]);
                fma2(acc[r], xv.u[0], uv.u[0]);
                fma2(acc[r], xv.u[1], uv.u[1]);
            }
        }
#pragma unroll
        for (int r = 0; r < 8; ++r) sm.xp[w * 8 + r][l] = fmaxf(hsum2(acc[r]), 0.f);
    }
    __syncthreads();      // G is cross-warp; xp rows stay warp-local

    {
        u64 acc[8];
#pragma unroll
        for (int r = 0; r < 8; ++r) acc[r] = 0ull;
#pragma unroll
        for (int k14 = 0; k14 < 8; ++k14) {
            int k1 = 4 * k14;
            F4 gv; gv.v = *reinterpret_cast<const float4*>(&sm.G[l][k1]);  // G symmetric
#pragma unroll
            for (int r = 0; r < 8; ++r) {
                F4 xv; xv.v = *reinterpret_cast<const float4*>(&sm.xp[w * 8 + r][k1]);
                fma2(acc[r], xv.u[0], gv.u[0]);
                fma2(acc[r], xv.u[1], gv.u[1]);
            }
        }
#pragma unroll
        for (int r = 0; r < 8; ++r) {
            float v = sm.xp[w * 8 + r][l] * hsum2(acc[r]);
#pragma unroll
            for (int o = 16; o; o >>= 1) v += __shfl_xor_sync(0xffffffffu, v, o);
            if (l == 0) out[row0 + w * 8 + r] = 1.f / (1.f + __expf(-v));
        }
    }
}

// =====================================================================
extern "C" void kernel_launch(void* const* d_in, const int* in_sizes, int n_in,
                              void* d_out, int out_size)
{
    const float* node = (const float*)d_in[0];
    const float* frag = (const float*)d_in[1];
    const float* Wg   = (const float*)d_in[2];
    const float* bg   = (const float*)d_in[3];
    const float* Ug   = (const float*)d_in[4];
    const float* Vg   = (const float*)d_in[5];
    const float* qg   = (const float*)d_in[6];
    const float* gW   = (const float*)d_in[7];
    const float* gB   = (const float*)d_in[8];
    float* out = (float*)d_out;

    cudaFuncSetAttribute(gemm_in_kernel, cudaFuncAttributeMaxDynamicSharedMemorySize, (int)sizeof(SmG));
    cudaFuncSetAttribute(layerA_kernel,  cudaFuncAttributeMaxDynamicSharedMemorySize, (int)sizeof(SmA));
    cudaFuncSetAttribute(layerB_kernel,  cudaFuncAttributeMaxDynamicSharedMemorySize, (int)sizeof(SmB));
    cudaFuncSetAttribute(final_kernel,   cudaFuncAttributeMaxDynamicSharedMemorySize, (int)sizeof(SmF));

    gemm_in_kernel<<<NBLKX + NBLKF, 256, sizeof(SmG)>>>(node, frag, Wg, bg);
    stats_kernel<<<1, 256>>>();
    yp_kernel<<<BGR * 5, 256>>>(Vg, qg);
    layerA_kernel<<<NBLKX, 256, sizeof(SmA)>>>(Ug, 1);   // launch #4 -> profiled
    merge_kernel<<<160, 256>>>();
    layerB_kernel<<<NBLKX, 256, sizeof(SmB)>>>(Vg, gW, gB);
    layerA_kernel<<<NBLKX, 256, sizeof(SmA)>>>(Ug, 0);
    merge_kernel<<<160, 256>>>();
    layerB_kernel<<<NBLKX, 256, sizeof(SmB)>>>(Vg, gW, gB);
    final_kernel<<<NBLKX, 256, sizeof(SmF)>>>(Ug, out);
}

// round 14
// speedup vs baseline: 1.9084x; 1.0827x over previous
#include <cuda_runtime.h>
#include <math.h>

#define BGR   32
#define NTOT  131072
#define NBLKX 2048
#define NBLKF 20

typedef unsigned long long u64;
union F4 { float4 v; u64 u[2]; };

__device__ __forceinline__ void fma2(u64& d, u64 a, u64 b) {
    asm("fma.rn.f32x2 %0, %1, %2, %0;" : "+l"(d) : "l"(a), "l"(b));
}
__device__ __forceinline__ float hsum2(u64 a) {
    unsigned lo, hi;
    asm("mov.b64 {%0,%1}, %2;" : "=r"(lo), "=r"(hi) : "l"(a));
    return __uint_as_float(lo) + __uint_as_float(hi);
}

// ---------------- device scratch (no runtime alloc) ----------------
__device__ __align__(16) float g_x[(size_t)NTOT * 128];
__device__ __align__(16) float g_I[(size_t)NTOT * 40];
__device__ __align__(16) float g_ypre[1280 * 128];
__device__ __align__(16) float g_yp[BGR * 40 * 32];
__device__ __align__(16) float g_G[BGR * 32 * 32];
__device__ float g_part[NBLKX * 2];
__device__ float g_partf[NBLKF * 2];
__device__ float g_scal[4];
__device__ float g_sm[BGR * 64 * 40];
__device__ float g_ss[BGR * 64 * 40];
__device__ float g_m[BGR * 40];
__device__ float g_si[BGR * 40];

// =====================================================================
// K1: out[rows][128] = in[rows][64] @ W^T + b ; LN partial sums
// =====================================================================
struct SmG {
    float in_sh[64][68];
    float Ws[128][68];
    float bias[128];
    float red[16];
};

__global__ __launch_bounds__(256, 2) void gemm_in_kernel(
    const float* __restrict__ node, const float* __restrict__ frag,
    const float* __restrict__ Wg, const float* __restrict__ bg)
{
    extern __shared__ char smraw[];
    SmG& sm = *reinterpret_cast<SmG*>(smraw);
    const int t = threadIdx.x, w = t >> 5, l = t & 31;
    const int sel = (blockIdx.x >= NBLKX);
    const int bid = sel ? (blockIdx.x - NBLKX) : blockIdx.x;
    const size_t row0 = (size_t)bid * 64;
    const float* inp = sel ? frag : node;
    float* outp  = sel ? g_ypre : g_x;
    float* partp = sel ? g_partf : g_part;

#pragma unroll
    for (int u = 0; u < 4; ++u) {
        int id = t + 256 * u;
        int r = id >> 4, cq = id & 15;
        *reinterpret_cast<float4*>(&sm.in_sh[r][cq * 4]) =
            *reinterpret_cast<const float4*>(inp + (row0 + r) * 64 + cq * 4);
    }
#pragma unroll
    for (int u = 0; u < 8; ++u) {
        int id = t + 256 * u;
        int d = id >> 4, f4 = id & 15;
        *reinterpret_cast<float4*>(&sm.Ws[d][f4 * 4]) =
            *reinterpret_cast<const float4*>(Wg + d * 64 + f4 * 4);
    }
    if (t < 128) sm.bias[t] = bg[t];
    __syncthreads();

    u64 acc[8][4];
#pragma unroll
    for (int r = 0; r < 8; ++r)
#pragma unroll
        for (int q = 0; q < 4; ++q) acc[r][q] = 0ull;

#pragma unroll
    for (int f4 = 0; f4 < 16; ++f4) {
        int f = f4 * 4;
        F4 wq[4];
#pragma unroll
        for (int q = 0; q < 4; ++q)
            wq[q].v = *reinterpret_cast<const float4*>(&sm.Ws[l + 32 * q][f]);
#pragma unroll
        for (int r = 0; r < 8; ++r) {
            F4 xv; xv.v = *reinterpret_cast<const float4*>(&sm.in_sh[w * 8 + r][f]);
#pragma unroll
            for (int q = 0; q < 4; ++q) {
                fma2(acc[r][q], xv.u[0], wq[q].u[0]);
                fma2(acc[r][q], xv.u[1], wq[q].u[1]);
            }
        }
    }

    float s1 = 0.f, s2 = 0.f;
#pragma unroll
    for (int r = 0; r < 8; ++r) {
        float* orow = outp + (row0 + w * 8 + r) * 128;
#pragma unroll
        for (int q = 0; q < 4; ++q) {
            float v = hsum2(acc[r][q]) + sm.bias[l + 32 * q];
            orow[l + 32 * q] = v;
            s1 += v; s2 += v * v;
        }
    }
#pragma unroll
    for (int o = 16; o; o >>= 1) {
        s1 += __shfl_xor_sync(0xffffffffu, s1, o);
        s2 += __shfl_xor_sync(0xffffffffu, s2, o);
    }
    if (l == 0) { sm.red[w] = s1; sm.red[8 + w] = s2; }
    __syncthreads();
    if (t == 0) {
        float S = 0.f, Q = 0.f;
        for (int i = 0; i < 8; ++i) { S += sm.red[i]; Q += sm.red[8 + i]; }
        partp[2 * bid]     = S;
        partp[2 * bid + 1] = Q;
    }
}

// =====================================================================
// K2: finalize LN scalars
// =====================================================================
__global__ void stats_kernel()
{
    __shared__ double sh[256];
    const int t = threadIdx.x;
    double s = 0.0, q = 0.0;
    for (int i = t; i < NBLKX; i += 256) { s += (double)g_part[2 * i]; q += (double)g_part[2 * i + 1]; }

    double S, Q, Sf, Qf;
    sh[t] = s; __syncthreads();
    for (int o = 128; o; o >>= 1) { if (t < o) sh[t] += sh[t + o]; __syncthreads(); }
    S = sh[0]; __syncthreads();

    sh[t] = q; __syncthreads();
    for (int o = 128; o; o >>= 1) { if (t < o) sh[t] += sh[t + o]; __syncthreads(); }
    Q = sh[0]; __syncthreads();

    sh[t] = (t < NBLKF) ? (double)g_partf[2 * t] : 0.0; __syncthreads();
    for (int o = 128; o; o >>= 1) { if (t < o) sh[t] += sh[t + o]; __syncthreads(); }
    Sf = sh[0]; __syncthreads();

    sh[t] = (t < NBLKF) ? (double)g_partf[2 * t + 1] : 0.0; __syncthreads();
    for (int o = 128; o; o >>= 1) { if (t < o) sh[t] += sh[t + o]; __syncthreads(); }
    Qf = sh[0];

    if (t == 0) {
        double nx = 16777216.0;
        double mx = S / nx, vx = Q / nx - mx * mx;
        g_scal[0] = (float)mx;
        g_scal[1] = (float)(1.0 / sqrt(vx + 1e-5));
        double ny = 163840.0;
        double my = Sf / ny, vy = Qf / ny - my * my;
        g_scal[2] = (float)my;
        g_scal[3] = (float)(1.0 / sqrt(vy + 1e-5));
    }
}

// =====================================================================
// K3: y_p = relu(q * relu(LN(ys) @ V)); grid = 32 graphs x 5 j-chunks
// =====================================================================
__global__ __launch_bounds__(256) void yp_kernel(
    const float* __restrict__ Vg, const float* __restrict__ qg)
{
    __shared__ float ys[8][132];
    __shared__ float Vt[32][132];
    __shared__ float qs[32];
    const int b = blockIdx.x / 5, jc = blockIdx.x % 5, t = threadIdx.x;
    const int j0 = jc * 8;
    const float m = g_scal[2], rs = g_scal[3];
#pragma unroll
    for (int u = 0; u < 4; ++u) {
        int id = t + 256 * u;
        ys[id >> 7][id & 127] = (g_ypre[b * 5120 + j0 * 128 + id] - m) * rs;
    }
#pragma unroll
    for (int u = 0; u < 16; ++u) {
        int id = t + 256 * u;
        Vt[id & 31][id >> 5] = Vg[id];
    }
    if (t < 32) qs[t] = qg[t];
    __syncthreads();

    const int j = t >> 5, k = t & 31;
    u64 a0 = 0ull, a1 = 0ull;
#pragma unroll
    for (int c4 = 0; c4 < 32; c4 += 2) {
        F4 y0; y0.v = *reinterpret_cast<const float4*>(&ys[j][c4 * 4]);
        F4 v0; v0.v = *reinterpret_cast<const float4*>(&Vt[k][c4 * 4]);
        F4 y1; y1.v = *reinterpret_cast<const float4*>(&ys[j][c4 * 4 + 4]);
        F4 v1; v1.v = *reinterpret_cast<const float4*>(&Vt[k][c4 * 4 + 4]);
        fma2(a0, y0.u[0], v0.u[0]);
        fma2(a0, y0.u[1], v0.u[1]);
        fma2(a1, y1.u[0], v1.u[0]);
        fma2(a1, y1.u[1], v1.u[1]);
    }
    float a = fmaxf(hsum2(a0) + hsum2(a1), 0.f);
    a = fmaxf(qs[k] * a, 0.f);
    g_yp[b * 1280 + (j0 + j) * 32 + k] = a;
}

// =====================================================================
// K4: layerA — R9-PROVEN kernel (journal: do not restructure)
// =====================================================================
struct SmA {
    float xs[64][128];
    float Ut[32][132];
    float yp[40][36];
    float xp[64][36];
    float red_m[8][40];
    float red_s[8][40];
};

__global__ __launch_bounds__(256, 3) void layerA_kernel(const float* __restrict__ Ug,
                                                        int do_norm)
{
    extern __shared__ char smraw[];
    SmA& sm = *reinterpret_cast<SmA*>(smraw);
    const int t = threadIdx.x, w = t >> 5, l = t & 31;
    const size_t row0 = (size_t)blockIdx.x * 64;
    const int b = blockIdx.x >> 6, blk = blockIdx.x & 63;

    if (do_norm) {
        const float m = g_scal[0], rs = g_scal[1];
#pragma unroll
        for (int u = 0; u < 8; ++u) {
            int id = t + 256 * u;
            int r = id >> 5, cq = id & 31;
            float* gp = g_x + (row0 + r) * 128 + cq * 4;
            float4 v = *reinterpret_cast<const float4*>(gp);
            v.x = (v.x - m) * rs; v.y = (v.y - m) * rs;
            v.z = (v.z - m) * rs; v.w = (v.w - m) * rs;
            *reinterpret_cast<float4*>(gp) = v;
            *reinterpret_cast<float4*>(&sm.xs[r][cq * 4]) = v;
        }
    } else {
#pragma unroll
        for (int u = 0; u < 8; ++u) {
            int id = t + 256 * u;
            int r = id >> 5, cq = id & 31;
            *reinterpret_cast<float4*>(&sm.xs[r][cq * 4]) =
                *reinterpret_cast<const float4*>(g_x + (row0 + r) * 128 + cq * 4);
        }
    }
#pragma unroll
    for (int u = 0; u < 16; ++u) {
        int id = t + 256 * u;
        sm.Ut[id & 31][id >> 5] = Ug[id];
    }
#pragma unroll
    for (int u = 0; u < 5; ++u) {
        int id = t + 256 * u;
        sm.yp[id >> 5][id & 31] = g_yp[b * 1280 + id];
    }
    __syncthreads();

    // xp = relu(x @ U)
    {
        u64 acc[8];
#pragma unroll
        for (int r = 0; r < 8; ++r) acc[r] = 0ull;
#pragma unroll
        for (int c4 = 0; c4 < 32; ++c4) {
            int c = c4 * 4;
            F4 uv; uv.v = *reinterpret_cast<const float4*>(&sm.Ut[l][c]);
#pragma unroll
            for (int r = 0; r < 8; ++r) {
                F4 xv; xv.v = *reinterpret_cast<const float4*>(&sm.xs[w * 8 + r][c]);
                fma2(acc[r], xv.u[0], uv.u[0]);
                fma2(acc[r], xv.u[1], uv.u[1]);
            }
        }
#pragma unroll
        for (int r = 0; r < 8; ++r) sm.xp[w * 8 + r][l] = fmaxf(hsum2(acc[r]), 0.f);
    }
    __syncwarp();

    // I = xp @ yp^T
    {
        const int j0 = l;
        const bool has1 = (l < 8);
        const int j1 = has1 ? (l + 32) : 39;
        u64 a0[8], a1[8];
#pragma unroll
        for (int r = 0; r < 8; ++r) { a0[r] = 0ull; a1[r] = 0ull; }
#pragma unroll
        for (int k4 = 0; k4 < 8; ++k4) {
            int k = k4 * 4;
            F4 y0; y0.v = *reinterpret_cast<const float4*>(&sm.yp[j0][k]);
            F4 y1; y1.v = *reinterpret_cast<const float4*>(&sm.yp[j1][k]);
#pragma unroll
            for (int r = 0; r < 8; ++r) {
                F4 xv; xv.v = *reinterpret_cast<const float4*>(&sm.xp[w * 8 + r][k]);
                fma2(a0[r], xv.u[0], y0.u[0]);
                fma2(a0[r], xv.u[1], y0.u[1]);
                fma2(a1[r], xv.u[0], y1.u[0]);
                fma2(a1[r], xv.u[1], y1.u[1]);
            }
        }
        float i0[8], i1[8];
#pragma unroll
        for (int r = 0; r < 8; ++r) { i0[r] = hsum2(a0[r]); i1[r] = hsum2(a1[r]); }
        float m0 = -1e30f, m1 = -1e30f;
#pragma unroll
        for (int r = 0; r < 8; ++r) { m0 = fmaxf(m0, i0[r]); m1 = fmaxf(m1, i1[r]); }
        float s0 = 0.f, s1v = 0.f;
#pragma unroll
        for (int r = 0; r < 8; ++r) { s0 += __expf(i0[r] - m0); s1v += __expf(i1[r] - m1); }
#pragma unroll
        for (int r = 0; r < 8; ++r) {
            size_t row = row0 + w * 8 + r;
            g_I[row * 40 + j0] = i0[r];
            if (has1) g_I[row * 40 + j1] = i1[r];
        }
        sm.red_m[w][j0] = m0; sm.red_s[w][j0] = s0;
        if (has1) { sm.red_m[w][j1] = m1; sm.red_s[w][j1] = s1v; }
    }
    __syncthreads();

    if (t < 40) {
        float m = sm.red_m[0][t], s = sm.red_s[0][t];
#pragma unroll
        for (int ww = 1; ww < 8; ++ww) {
            float bm = sm.red_m[ww][t], bs = sm.red_s[ww][t];
            float mn = fmaxf(m, bm);
            s = s * __expf(m - mn) + bs * __expf(bm - mn);
            m = mn;
        }
        int idx = (b * 64 + blk) * 40 + t;
        g_sm[idx] = m; g_ss[idx] = s;
    }
}

// =====================================================================
// K5: merge softmax partials (blocks 0..159) + optional gram (160..191)
// =====================================================================
__global__ __launch_bounds__(256) void merge_kernel()
{
    __shared__ float yps[40][33];
    const int t = threadIdx.x;

    if (blockIdx.x >= 160) {
        // gram for graph b: G = yp^T yp (same order as old gram kernel)
        const int b = blockIdx.x - 160;
#pragma unroll
        for (int u = 0; u < 5; ++u) {
            int id = t + 256 * u;
            yps[id >> 5][id & 31] = g_yp[b * 1280 + id];
        }
        __syncthreads();
#pragma unroll
        for (int u = 0; u < 4; ++u) {
            int id = t + 256 * u;
            int k1 = id >> 5, k2 = id & 31;
            float acc = 0.f;
#pragma unroll
            for (int j = 0; j < 40; ++j) acc += yps[j][k1] * yps[j][k2];
            g_G[b * 1024 + id] = acc;
        }
        return;
    }

    const int w = t >> 5, l = t & 31;
    const int widx = blockIdx.x * 8 + w;
    const int b = widx / 40, j = widx % 40;
    float m1 = g_sm[(b * 64 + l) * 40 + j];
    float s1 = g_ss[(b * 64 + l) * 40 + j];
    float m2 = g_sm[(b * 64 + l + 32) * 40 + j];
    float s2 = g_ss[(b * 64 + l + 32) * 40 + j];
    float m = fmaxf(m1, m2);
    float s = s1 * __expf(m1 - m) + s2 * __expf(m2 - m);
#pragma unroll
    for (int o = 16; o; o >>= 1) {
        float bm = __shfl_xor_sync(0xffffffffu, m, o);
        float bs = __shfl_xor_sync(0xffffffffu, s, o);
        float mn = fmaxf(m, bm);
        s = s * __expf(m - mn) + bs * __expf(bm - mn);
        m = mn;
    }
    if (l == 0) {
        g_m[b * 40 + j]  = m;
        g_si[b * 40 + j] = 1.f / s;
    }
}

// =====================================================================
// K6: layerB — EXACT R9 kernel (journal rule: do not modify)
// =====================================================================
struct SmB {
    float xs[64][128];
    float a[64][44];
    float ypT[32][44];
    float Vs[128][36];
    float h[64][36];
    float gw[256];
    float gb;
};

__global__ __launch_bounds__(256, 2) void layerB_kernel(
    const float* __restrict__ Vg, const float* __restrict__ gWp,
    const float* __restrict__ gBp)
{
    extern __shared__ char smraw[];
    SmB& sm = *reinterpret_cast<SmB*>(smraw);
    const int t = threadIdx.x, w = t >> 5, l = t & 31;
    const size_t row0 = (size_t)blockIdx.x * 64;
    const int b = blockIdx.x >> 6;

#pragma unroll
    for (int u = 0; u < 8; ++u) {
        int id = t + 256 * u;
        int r = id >> 5, cq = id & 31;
        *reinterpret_cast<float4*>(&sm.xs[r][cq * 4]) =
            *reinterpret_cast<const float4*>(g_x + (row0 + r) * 128 + cq * 4);
    }
#pragma unroll
    for (int u = 0; u < 4; ++u) {
        int id = t + 256 * u;
        int d = id >> 3, k4 = id & 7;
        *reinterpret_cast<float4*>(&sm.Vs[d][k4 * 4]) =
            *reinterpret_cast<const float4*>(Vg + d * 32 + k4 * 4);
    }
#pragma unroll
    for (int u = 0; u < 5; ++u) {
        int id = t + 256 * u;
        sm.ypT[id & 31][id >> 5] = g_yp[b * 1280 + id];
    }
    sm.gw[t] = gWp[t];
    if (t == 0) sm.gb = gBp[0];
#pragma unroll
    for (int u = 0; u < 10; ++u) {
        int id = t + 256 * u;
        int r = id / 40, j = id - r * 40;
        float v = g_I[row0 * 40 + id];
        sm.a[r][j] = __expf(v - g_m[b * 40 + j]) * g_si[b * 40 + j];
    }
    __syncthreads();

    {
        u64 acc[8];
#pragma unroll
        for (int r = 0; r < 8; ++r) acc[r] = 0ull;
#pragma unroll
        for (int j4 = 0; j4 < 10; ++j4) {
            int j = j4 * 4;
            F4 yv; yv.v = *reinterpret_cast<const float4*>(&sm.ypT[l][j]);
#pragma unroll
            for (int r = 0; r < 8; ++r) {
                F4 av; av.v = *reinterpret_cast<const float4*>(&sm.a[w * 8 + r][j]);
                fma2(acc[r], av.u[0], yv.u[0]);
                fma2(acc[r], av.u[1], yv.u[1]);
            }
        }
#pragma unroll
        for (int r = 0; r < 8; ++r) sm.h[w * 8 + r][l] = fmaxf(hsum2(acc[r]), 0.f);
    }
    __syncwarp();

    {
        u64 acc[8][4];
#pragma unroll
        for (int r = 0; r < 8; ++r)
#pragma unroll
            for (int q = 0; q < 4; ++q) acc[r][q] = 0ull;

#pragma unroll
        for (int k4 = 0; k4 < 8; ++k4) {
            int k = 4 * k4;
            F4 vq[4];
#pragma unroll
            for (int q = 0; q < 4; ++q)
                vq[q].v = *reinterpret_cast<const float4*>(&sm.Vs[l + 32 * q][k]);
#pragma unroll
            for (int r = 0; r < 8; ++r) {
                F4 hv; hv.v = *reinterpret_cast<const float4*>(&sm.h[w * 8 + r][k]);
#pragma unroll
                for (int q = 0; q < 4; ++q) {
                    fma2(acc[r][q], hv.u[0], vq[q].u[0]);
                    fma2(acc[r][q], hv.u[1], vq[q].u[1]);
                }
            }
        }
        float gb = sm.gb;
#pragma unroll
        for (int r = 0; r < 8; ++r) {
            float gp = 0.f;
            float xv[4], hc[4];
#pragma unroll
            for (int q = 0; q < 4; ++q) {
                int d = l + 32 * q;
                hc[q] = hsum2(acc[r][q]);
                xv[q] = sm.xs[w * 8 + r][d];
                gp += xv[q] * sm.gw[d] + hc[q] * sm.gw[128 + d];
            }
#pragma unroll
            for (int o = 16; o; o >>= 1) gp += __shfl_xor_sync(0xffffffffu, gp, o);
            float z = 1.f / (1.f + __expf(-(gp + gb)));
            float* orow = g_x + (row0 + w * 8 + r) * 128;
#pragma unroll
            for (int q = 0; q < 4; ++q) {
                int d = l + 32 * q;
                orow[d] = (1.f - z) * xv[q] + z * hc[q];
            }
        }
    }
}

// =====================================================================
// K7: final — EXACT R11 kernel (reads g_G)
// =====================================================================
struct SmF {
    float xs[64][128];
    float Ut[32][132];
    float G[32][36];
    float xp[64][36];
};

__global__ __launch_bounds__(256, 3) void final_kernel(
    const float* __restrict__ Ug, float* __restrict__ out)
{
    extern __shared__ char smraw[];
    SmF& sm = *reinterpret_cast<SmF*>(smraw);
    const int t = threadIdx.x, w = t >> 5, l = t & 31;
    const size_t row0 = (size_t)blockIdx.x * 64;
    const int b = blockIdx.x >> 6;

#pragma unroll
    for (int u = 0; u < 8; ++u) {
        int id = t + 256 * u;
        int r = id >> 5, cq = id & 31;
        *reinterpret_cast<float4*>(&sm.xs[r][cq * 4]) =
            *reinterpret_cast<const float4*>(g_x + (row0 + r) * 128 + cq * 4);
    }
#pragma unroll
    for (int u = 0; u < 16; ++u) {
        int id = t + 256 * u;
        sm.Ut[id & 31][id >> 5] = Ug[id];
    }
#pragma unroll
    for (int u = 0; u < 4; ++u) {
        int id = t + 256 * u;
        int k1 = id >> 5, k2 = id & 31;
        sm.G[k1][k2] = g_G[b * 1024 + id];
    }
    __syncthreads();

    {
        u64 acc[8];
#pragma unroll
        for (int r = 0; r < 8; ++r) acc[r] = 0ull;
#pragma unroll
        for (int c4 = 0; c4 < 32; ++c4) {
            int c = c4 * 4;
            F4 uv; uv.v = *reinterpret_cast<const float4*>(&sm.Ut[l][c]);
#pragma unroll
            for (int r = 0; r < 8; ++r) {
                F4 xv; xv.v = *reinterpret_cast<const float4*>(&sm.xs[w * 8 + r][c]);
                fma2(acc[r], xv.u[0], uv.u[0]);
                fma2(acc[r], xv.u[1], uv.u[1]);
            }
        }
#pragma unroll
        for (int r = 0; r < 8; ++r) sm.xp[w * 8 + r][l] = fmaxf(hsum2(acc[r]), 0.f);
    }
    __syncwarp();

    {
        u64 acc[8];
#pragma unroll
        for (int r = 0; r < 8; ++r) acc[r] = 0ull;
#pragma unroll
        for (int k14 = 0; k14 < 8; ++k14) {
            int k1 = 4 * k14;
            F4 gv; gv.v = *reinterpret_cast<const float4*>(&sm.G[l][k1]);
#pragma unroll
            for (int r = 0; r < 8; ++r) {
                F4 xv; xv.v = *reinterpret_cast<const float4*>(&sm.xp[w * 8 + r][k1]);
                fma2(acc[r], xv.u[0], gv.u[0]);
                fma2(acc[r], xv.u[1], gv.u[1]);
            }
        }
#pragma unroll
        for (int r = 0; r < 8; ++r) {
            float v = sm.xp[w * 8 + r][l] * hsum2(acc[r]);
#pragma unroll
            for (int o = 16; o; o >>= 1) v += __shfl_xor_sync(0xffffffffu, v, o);
            if (l == 0) out[row0 + w * 8 + r] = 1.f / (1.f + __expf(-v));
        }
    }
}

// =====================================================================
extern "C" void kernel_launch(void* const* d_in, const int* in_sizes, int n_in,
                              void* d_out, int out_size)
{
    const float* node = (const float*)d_in[0];
    const float* frag = (const float*)d_in[1];
    const float* Wg   = (const float*)d_in[2];
    const float* bg   = (const float*)d_in[3];
    const float* Ug   = (const float*)d_in[4];
    const float* Vg   = (const float*)d_in[5];
    const float* qg   = (const float*)d_in[6];
    const float* gW   = (const float*)d_in[7];
    const float* gB   = (const float*)d_in[8];
    float* out = (float*)d_out;

    cudaFuncSetAttribute(gemm_in_kernel, cudaFuncAttributeMaxDynamicSharedMemorySize, (int)sizeof(SmG));
    cudaFuncSetAttribute(layerA_kernel,  cudaFuncAttributeMaxDynamicSharedMemorySize, (int)sizeof(SmA));
    cudaFuncSetAttribute(layerB_kernel,  cudaFuncAttributeMaxDynamicSharedMemorySize, (int)sizeof(SmB));
    cudaFuncSetAttribute(final_kernel,   cudaFuncAttributeMaxDynamicSharedMemorySize, (int)sizeof(SmF));

    gemm_in_kernel<<<NBLKX + NBLKF, 256, sizeof(SmG)>>>(node, frag, Wg, bg);
    stats_kernel<<<1, 256>>>();
    yp_kernel<<<BGR * 5, 256>>>(Vg, qg);
    layerA_kernel<<<NBLKX, 256, sizeof(SmA)>>>(Ug, 1);   // launch #4 -> profiled
    merge_kernel<<<192, 256>>>();                        // merge + gram (32 extra blocks)
    layerB_kernel<<<NBLKX, 256, sizeof(SmB)>>>(Vg, gW, gB);
    layerA_kernel<<<NBLKX, 256, sizeof(SmA)>>>(Ug, 0);
    merge_kernel<<<160, 256>>>();                        // merge only
    layerB_kernel<<<NBLKX, 256, sizeof(SmB)>>>(Vg, gW, gB);
    final_kernel<<<NBLKX, 256, sizeof(SmF)>>>(Ug, out);
}